// round 16
// baseline (speedup 1.0000x reference)
#include <cuda_runtime.h>

// Causal FIR: y[r][t] = sum_{k=0}^{15} b[k] * x[r][t-k], zero init per row.
// x: [64, 480000] f32, b: [16] f32, y: [64, 480000] f32.
//
// R15 ncu: issue 49.5, DRAM 64.4, occ 37.1 — latency co-bound, no pipe
// saturated. This round fully unrolls the 5-tile chain: slide MOVs die by
// renaming, pointer adds become [R+imm] LDG offsets, loop overhead and
// predicated nv zero-inits fold away, and ptxas can hoist next-tile loads
// across tile boundaries for deeper MLP. launch_bounds(128,7) caps the
// register budget at 72 so unrolled hoisting can't balloon pressure.
// Dataflow unchanged: exact-once coalesced LDG.128, register-chained halo,
// merged 64-bit shuffles (select-before-rotate), packed fma.rn.f32x2.

#define T_LEN    480000
#define NTAPS    16
#define BATCH    64
#define TILE     256                       // floats per warp tile (2 sub-panels)
#define N_TILES  (T_LEN / TILE)            // 1875 tiles per row
#define T_PER    5                         // tiles per warp chain
#define N_CHAIN  (N_TILES / T_PER)         // 375 chains per row
#define WARPS_PB 4
#define BLOCK    (WARPS_PB * 32)           // 128 threads

typedef unsigned long long u64;

__device__ __forceinline__ u64 pack2(float lo, float hi) {
    u64 r; asm("mov.b64 %0, {%1, %2};" : "=l"(r) : "f"(lo), "f"(hi)); return r;
}
__device__ __forceinline__ void unpack2(u64 v, float& lo, float& hi) {
    asm("mov.b64 {%0, %1}, %2;" : "=f"(lo), "=f"(hi) : "l"(v));
}
// acc += a * b : two independent fp32 FMAs in one SASS FFMA2
__device__ __forceinline__ void fma2(u64& acc, u64 a, u64 b) {
    asm("fma.rn.f32x2 %0, %1, %2, %0;" : "+l"(acc) : "l"(a), "l"(b));
}
// r = a * b : packed multiply (first use of each accumulator)
__device__ __forceinline__ u64 mul2(u64 a, u64 b) {
    u64 r; asm("mul.rn.f32x2 %0, %1, %2;" : "=l"(r) : "l"(a), "l"(b)); return r;
}
__device__ __forceinline__ u64 shfl64(u64 v, int src) {
    return __shfl_sync(0xffffffffu, v, src);
}

__global__ __launch_bounds__(BLOCK, 7)
void fir_apply_kernel(const float* __restrict__ x,
                      const float* __restrict__ b,
                      float* __restrict__ y)
{
    const int lane  = threadIdx.x & 31;
    const int warp  = threadIdx.x >> 5;
    const int chain = blockIdx.x * WARPS_PB + warp;
    if (chain >= N_CHAIN) return;            // warp-uniform exit
    const int row = blockIdx.y;

    const float4* __restrict__ x4 = reinterpret_cast<const float4*>(x + (size_t)row * T_LEN);
    float4* __restrict__ y4 = reinterpret_cast<float4*>(y + (size_t)row * T_LEN);

    // ---- taps, packed (b[k], b[k]) — amortized over the 5-tile chain ----
    u64 bbp[NTAPS];
    {
        const float4* b4 = reinterpret_cast<const float4*>(b);
        float4 q0 = __ldg(b4 + 0), q1 = __ldg(b4 + 1),
               q2 = __ldg(b4 + 2), q3 = __ldg(b4 + 3);
        bbp[0]  = pack2(q0.x, q0.x); bbp[1]  = pack2(q0.y, q0.y);
        bbp[2]  = pack2(q0.z, q0.z); bbp[3]  = pack2(q0.w, q0.w);
        bbp[4]  = pack2(q1.x, q1.x); bbp[5]  = pack2(q1.y, q1.y);
        bbp[6]  = pack2(q1.z, q1.z); bbp[7]  = pack2(q1.w, q1.w);
        bbp[8]  = pack2(q2.x, q2.x); bbp[9]  = pack2(q2.y, q2.y);
        bbp[10] = pack2(q2.z, q2.z); bbp[11] = pack2(q2.w, q2.w);
        bbp[12] = pack2(q3.x, q3.x); bbp[13] = pack2(q3.y, q3.y);
        bbp[14] = pack2(q3.z, q3.z); bbp[15] = pack2(q3.w, q3.w);
    }

    const int pb4 = chain * T_PER * (TILE / 4);   // float4 index of chain base

    // halo: lanes 28..31 hold x[pb-16+4(lane-28) .. +3]; chain 0 -> zeros
    float4 hv = make_float4(0.f, 0.f, 0.f, 0.f);
    if (chain > 0 && lane >= 28)
        hv = __ldg(x4 + (pb4 - 4 + (lane - 28)));

    const float4* __restrict__ xp = x4 + pb4 + lane;
    float4* __restrict__ yp = y4 + pb4 + lane;

    float4 v0 = __ldg(xp);           // sub-panel 0: x[t0..t0+3]
    float4 v1 = __ldg(xp + 32);      // sub-panel 1: x[t0+128..t0+131]

    // merge predicates (lane-invariant across the chain)
    const bool p28 = (lane >= 28);   // d = 4
    const bool p29 = (lane >= 29);   // d = 3
    const bool p30 = (lane >= 30);   // d = 2
    const bool p31 = (lane >= 31);   // d = 1

    #pragma unroll
    for (int t = 0; t < T_PER; t++) {
        // prefetch next tile (statically resolved after full unroll)
        float4 nv0 = make_float4(0.f, 0.f, 0.f, 0.f);
        float4 nv1 = make_float4(0.f, 0.f, 0.f, 0.f);
        if (t < T_PER - 1) {
            nv0 = __ldg(xp + 64 * (t + 1));
            nv1 = __ldg(xp + 64 * (t + 1) + 32);
        }

        // pair registers: pv = (halo_p0, halo_p1) = (hv, v0)
        //                 cv = (cur_p0,  cur_p1)  = (v0, v1)
        u64 pv[4], cv[4];
        pv[0] = pack2(hv.x, v0.x); cv[0] = pack2(v0.x, v1.x);
        pv[1] = pack2(hv.y, v0.y); cv[1] = pack2(v0.y, v1.y);
        pv[2] = pack2(hv.z, v0.z); cv[2] = pack2(v0.z, v1.z);
        pv[3] = pack2(hv.w, v0.w); cv[3] = pack2(v0.w, v1.w);

        u64 a0, a1, a2, a3;

        // window pair wp[m] = (x[t0-16+m], x[t0+112+m]).
        // acc[jo] += bbp[k] * wp[16+jo-k]  <=>  wp[m] feeds k = 16+jo-m.

        // ---- d = 4: wp[1..3]  (wp[0] would need tap k=16 -> skipped) ----
        {
            const int src = (lane - 4) & 31;
            u64 w1 = shfl64(p28 ? pv[1] : cv[1], src);
            u64 w2 = shfl64(p28 ? pv[2] : cv[2], src);
            u64 w3 = shfl64(p28 ? pv[3] : cv[3], src);
            a0 = mul2(bbp[15], w1);
            fma2(a0, bbp[14], w2); a1 = mul2(bbp[15], w2);
            fma2(a0, bbp[13], w3); fma2(a1, bbp[14], w3);
            a2 = mul2(bbp[15], w3);
        }
        // ---- d = 3: wp[4+j], k = 12 + jo - j ----
        {
            const int src = (lane - 3) & 31;
            {   // j = 0: first use of a3
                u64 w = shfl64(p29 ? pv[0] : cv[0], src);
                fma2(a0, bbp[12], w); fma2(a1, bbp[13], w);
                fma2(a2, bbp[14], w); a3 = mul2(bbp[15], w);
            }
            #pragma unroll
            for (int j = 1; j < 4; j++) {
                u64 w = shfl64(p29 ? pv[j] : cv[j], src);
                fma2(a0, bbp[12 - j], w); fma2(a1, bbp[13 - j], w);
                fma2(a2, bbp[14 - j], w); fma2(a3, bbp[15 - j], w);
            }
        }
        // ---- d = 2: wp[8+j], k = 8 + jo - j ----
        {
            const int src = (lane - 2) & 31;
            #pragma unroll
            for (int j = 0; j < 4; j++) {
                u64 w = shfl64(p30 ? pv[j] : cv[j], src);
                fma2(a0, bbp[8 - j], w);  fma2(a1, bbp[9 - j], w);
                fma2(a2, bbp[10 - j], w); fma2(a3, bbp[11 - j], w);
            }
        }
        // ---- d = 1: wp[12+j], k = 4 + jo - j ----
        {
            const int src = (lane - 1) & 31;
            #pragma unroll
            for (int j = 0; j < 4; j++) {
                u64 w = shfl64(p31 ? pv[j] : cv[j], src);
                fma2(a0, bbp[4 - j], w); fma2(a1, bbp[5 - j], w);
                fma2(a2, bbp[6 - j], w); fma2(a3, bbp[7 - j], w);
            }
        }
        // ---- center: wp[16+j] = cv[j], k = jo - j (jo >= j) ----
        fma2(a0, bbp[0], cv[0]); fma2(a1, bbp[1], cv[0]);
        fma2(a2, bbp[2], cv[0]); fma2(a3, bbp[3], cv[0]);
        fma2(a1, bbp[0], cv[1]); fma2(a2, bbp[1], cv[1]);
        fma2(a3, bbp[2], cv[1]);
        fma2(a2, bbp[0], cv[2]); fma2(a3, bbp[1], cv[2]);
        fma2(a3, bbp[0], cv[3]);

        // ---- unpack + coalesced stores (panel0, panel1) ----
        float l0, h0, l1, h1, l2, h2, l3, h3;
        unpack2(a0, l0, h0); unpack2(a1, l1, h1);
        unpack2(a2, l2, h2); unpack2(a3, l3, h3);
        yp[64 * t]      = make_float4(l0, l1, l2, l3);
        yp[64 * t + 32] = make_float4(h0, h1, h2, h3);

        // slide the chain (pure renaming after unroll; dead on last iter)
        hv = v1;
        v0 = nv0;
        v1 = nv1;
    }
}

extern "C" void kernel_launch(void* const* d_in, const int* in_sizes, int n_in,
                              void* d_out, int out_size)
{
    const float* x = (const float*)d_in[0];   // [64, 480000] f32
    const float* b = (const float*)d_in[1];   // [16] f32
    float* y = (float*)d_out;                 // [64, 480000] f32

    dim3 grid((N_CHAIN + WARPS_PB - 1) / WARPS_PB, BATCH, 1);   // (94, 64)
    fir_apply_kernel<<<grid, BLOCK>>>(x, b, y);
}